// round 17
// baseline (speedup 1.0000x reference)
#include <cuda_runtime.h>
#include <cuda_fp16.h>
#include <math.h>
#include <cstdint>

// Problem constants
#define BB 4
#define LL 1024
#define DD 512
#define NN 16
#define NLAYER 2
#define NCH 32
#define LCH 32

#define BLD (BB*LL*DD)
#define BLN (BB*LL*NN)
#define CHN (BB*NCH*DD*NN)

#define MM (BB*LL)      // 4096 rows
#define KC 1024         // concatenated K (2x512): [Xh|Xl] x [Wh|Wh]
#define NW 576          // widened N for fused dt+B+C gemm
#define NBAR 288        // persistent grid size

// Scratch
__device__ float g_dt[BLD];
__device__ float g_Bm[BLN];
__device__ float g_Cm[BLN];
__device__ float g_P[CHN];
__device__ float g_He[CHN];
__device__ float g_carry[CHN];
__device__ float g_beff[DD];
__device__ volatile unsigned g_barc[12];
__device__ __half g_Xcat0[(size_t)MM * KC];       // [Xh | Xl]
__device__ __half g_Xcat1[(size_t)MM * KC];       // z split (also temp Wlin2 split)
__device__ __half g_Wcat[5 * (size_t)NW * KC];    // slots: 0,1=Wdt; 2=Wlin0; 3=Wdec; 4=F

__device__ __forceinline__ float softplusf(float x) {
    return fmaxf(x, 0.f) + log1pf(__expf(-fabsf(x)));
}

__device__ __forceinline__ uint32_t smem_u32(const void* p) {
    uint32_t a;
    asm("{ .reg .u64 t; cvta.to.shared.u64 t, %1; cvt.u32.u64 %0, t; }" : "=r"(a) : "l"(p));
    return a;
}

__device__ __forceinline__ uint32_t swz(int r, int c) {
    return ((uint32_t)r << 7) + ((uint32_t)(c ^ (r & 7)) << 4);
}

// grid barrier: all NBAR blocks co-resident by construction
__device__ __forceinline__ void gbar(int i) {
    __threadfence();
    __syncthreads();
    if (threadIdx.x == 0) {
        atomicAdd((unsigned*)&g_barc[i], 1u);
        while (g_barc[i] < (unsigned)NBAR) {}
    }
    __syncthreads();
    __threadfence();
}

#define BK 64
#define STG 3
#define ABYTES 16384
#define BBYTES 8192
#define STAGE_BYTES (ABYTES + BBYTES)
#define TC_SMEM (STG * STAGE_BYTES)

// ---------------------------------------------------------------------------
// GEMM tile: mainloop + epilogue. EPI: 0 = bias -> Cp; 1 = dt softplus ->
// g_dt + Bm/Cm cols>=512; 2 = bias + fp16 split -> xoutp; 3 = F transpose
// split -> slot 4.
// ---------------------------------------------------------------------------
template<int EPI>
__device__ void gemm_tile(int bn, int bm, const __half* __restrict__ Aop,
                          const __half* __restrict__ Bop, const float* __restrict__ bias,
                          const float* __restrict__ bBp, const float* __restrict__ bCp,
                          float* __restrict__ Cp, __half* __restrict__ xoutp)
{
    extern __shared__ char smem[];
    uint32_t sbase = smem_u32(smem);
    int tid = threadIdx.x, wid = tid >> 5, lane = tid & 31;
    int wm = wid & 3, wn = wid >> 2;
    int lrow = ((lane >> 3) & 1) * 8 + (lane & 7);
    int lck = lane >> 4;
    uint32_t aoff[2][4], boff[2][4];
    #pragma unroll
    for (int mt = 0; mt < 2; mt++)
        #pragma unroll
        for (int ks = 0; ks < 4; ks++)
            aoff[mt][ks] = swz(wm * 32 + mt * 16 + lrow, ks * 2 + lck);
    #pragma unroll
    for (int nt = 0; nt < 2; nt++)
        #pragma unroll
        for (int ks = 0; ks < 4; ks++)
            boff[nt][ks] = ABYTES + swz(wn * 32 + nt * 16 + lrow, ks * 2 + lck);
    int ra = tid >> 1, ca0 = (tid & 1) * 4;
    int rb = tid >> 2, cb0 = (tid & 3) * 2;
    const __half* gA = Aop + (size_t)(bm + ra) * KC + ca0 * 8;
    const __half* gB = Bop + (size_t)(bn + rb) * KC + cb0 * 8;
    uint32_t dA[4], dB[2];
    #pragma unroll
    for (int i = 0; i < 4; i++) dA[i] = swz(ra, ca0 + i);
    #pragma unroll
    for (int i = 0; i < 2; i++) dB[i] = ABYTES + swz(rb, cb0 + i);

    float acc[2][4][4];
    #pragma unroll
    for (int i = 0; i < 2; i++)
        #pragma unroll
        for (int j = 0; j < 4; j++)
            #pragma unroll
            for (int q = 0; q < 4; q++) acc[i][j][q] = 0.f;

    const int NKB = KC / BK;    // 16

    #pragma unroll
    for (int s = 0; s < STG - 1; s++) {
        uint32_t st = sbase + s * STAGE_BYTES;
        int ko = s * BK;
        #pragma unroll
        for (int i = 0; i < 4; i++)
            asm volatile("cp.async.cg.shared.global [%0], [%1], 16;" :: "r"(st + dA[i]), "l"(gA + ko + i * 8));
        #pragma unroll
        for (int i = 0; i < 2; i++)
            asm volatile("cp.async.cg.shared.global [%0], [%1], 16;" :: "r"(st + dB[i]), "l"(gB + ko + i * 8));
        asm volatile("cp.async.commit_group;" ::: "memory");
    }

    uint32_t bufA[2][2][4], bufB[2][2][4];
    int sbuf = 0;
    for (int kb = 0; kb < NKB; kb++) {
        asm volatile("cp.async.wait_group %0;" :: "n"(STG - 2) : "memory");
        __syncthreads();
        int knext = kb + STG - 1;
        if (knext < NKB) {
            int sn = knext % STG;
            uint32_t st = sbase + sn * STAGE_BYTES;
            int ko = knext * BK;
            #pragma unroll
            for (int i = 0; i < 4; i++)
                asm volatile("cp.async.cg.shared.global [%0], [%1], 16;" :: "r"(st + dA[i]), "l"(gA + ko + i * 8));
            #pragma unroll
            for (int i = 0; i < 2; i++)
                asm volatile("cp.async.cg.shared.global [%0], [%1], 16;" :: "r"(st + dB[i]), "l"(gB + ko + i * 8));
        }
        asm volatile("cp.async.commit_group;" ::: "memory");

        uint32_t st = sbase + sbuf * STAGE_BYTES;
        #pragma unroll
        for (int mt = 0; mt < 2; mt++)
            asm volatile("ldmatrix.sync.aligned.m8n8.x4.shared.b16 {%0,%1,%2,%3}, [%4];"
                         : "=r"(bufA[0][mt][0]), "=r"(bufA[0][mt][1]),
                           "=r"(bufA[0][mt][2]), "=r"(bufA[0][mt][3])
                         : "r"(st + aoff[mt][0]));
        #pragma unroll
        for (int nt = 0; nt < 2; nt++)
            asm volatile("ldmatrix.sync.aligned.m8n8.x4.shared.b16 {%0,%1,%2,%3}, [%4];"
                         : "=r"(bufB[0][nt][0]), "=r"(bufB[0][nt][1]),
                           "=r"(bufB[0][nt][2]), "=r"(bufB[0][nt][3])
                         : "r"(st + boff[nt][0]));
        #pragma unroll
        for (int ks = 0; ks < 4; ks++) {
            int cb = ks & 1, nb = cb ^ 1;
            if (ks < 3) {
                #pragma unroll
                for (int mt = 0; mt < 2; mt++)
                    asm volatile("ldmatrix.sync.aligned.m8n8.x4.shared.b16 {%0,%1,%2,%3}, [%4];"
                                 : "=r"(bufA[nb][mt][0]), "=r"(bufA[nb][mt][1]),
                                   "=r"(bufA[nb][mt][2]), "=r"(bufA[nb][mt][3])
                                 : "r"(st + aoff[mt][ks + 1]));
                #pragma unroll
                for (int nt = 0; nt < 2; nt++)
                    asm volatile("ldmatrix.sync.aligned.m8n8.x4.shared.b16 {%0,%1,%2,%3}, [%4];"
                                 : "=r"(bufB[nb][nt][0]), "=r"(bufB[nb][nt][1]),
                                   "=r"(bufB[nb][nt][2]), "=r"(bufB[nb][nt][3])
                                 : "r"(st + boff[nt][ks + 1]));
            }
            #pragma unroll
            for (int mt = 0; mt < 2; mt++)
                #pragma unroll
                for (int nt = 0; nt < 2; nt++)
                    #pragma unroll
                    for (int nf = 0; nf < 2; nf++)
                        asm volatile(
                            "mma.sync.aligned.m16n8k16.row.col.f32.f16.f16.f32 "
                            "{%0,%1,%2,%3}, {%4,%5,%6,%7}, {%8,%9}, {%0,%1,%2,%3};"
                            : "+f"(acc[mt][nt * 2 + nf][0]), "+f"(acc[mt][nt * 2 + nf][1]),
                              "+f"(acc[mt][nt * 2 + nf][2]), "+f"(acc[mt][nt * 2 + nf][3])
                            : "r"(bufA[cb][mt][0]), "r"(bufA[cb][mt][1]),
                              "r"(bufA[cb][mt][2]), "r"(bufA[cb][mt][3]),
                              "r"(bufB[cb][nt][nf]), "r"(bufB[cb][nt][2 + nf]));
        }
        sbuf++;
        if (sbuf == STG) sbuf = 0;
    }
    asm volatile("cp.async.wait_group 0;" ::: "memory");

    // epilogue
    int mbase = bm + wm * 32 + (lane >> 2);
    int nbase = bn + wn * 32 + (lane & 3) * 2;
    __half* slot4 = g_Wcat + (size_t)4 * NW * KC;
    #pragma unroll
    for (int mt = 0; mt < 2; mt++) {
        #pragma unroll
        for (int jf = 0; jf < 4; jf++) {
            int col = nbase + (jf >> 1) * 16 + (jf & 1) * 8;
            int m0 = mbase + mt * 16;
            if (EPI == 3) {
                #pragma unroll
                for (int q = 0; q < 4; q++) {
                    int mm = m0 + (q >> 1) * 8;
                    int cc = col + (q & 1);
                    __half h = __float2half_rn(acc[mt][jf][q]);
                    slot4[(size_t)cc * KC + mm]       = h;
                    slot4[(size_t)cc * KC + mm + 512] = h;
                }
                continue;
            }
            float b0, b1;
            if (EPI == 1 && col >= 512) {
                if (col < 528)      { b0 = bBp[col - 512]; b1 = bBp[col - 511]; }
                else if (col < 544) { b0 = bCp[col - 528]; b1 = bCp[col - 527]; }
                else                { b0 = 0.f; b1 = 0.f; }
            } else {
                b0 = bias[col]; b1 = bias[col + 1];
            }
            float v0 = acc[mt][jf][0] + b0, v1 = acc[mt][jf][1] + b1;
            float v2 = acc[mt][jf][2] + b0, v3 = acc[mt][jf][3] + b1;

            if (EPI == 1) {
                if (col >= 512) {
                    if (col < 528) {
                        int n = col - 512;
                        *(float2*)(g_Bm + (size_t)m0 * NN + n)       = make_float2(v0, v1);
                        *(float2*)(g_Bm + (size_t)(m0 + 8) * NN + n) = make_float2(v2, v3);
                    } else if (col < 544) {
                        int n = col - 528;
                        *(float2*)(g_Cm + (size_t)m0 * NN + n)       = make_float2(v0, v1);
                        *(float2*)(g_Cm + (size_t)(m0 + 8) * NN + n) = make_float2(v2, v3);
                    }
                    continue;
                }
                v0 = softplusf(v0); v1 = softplusf(v1); v2 = softplusf(v2); v3 = softplusf(v3);
                *(float2*)(g_dt + (size_t)m0 * DD + col)       = make_float2(v0, v1);
                *(float2*)(g_dt + (size_t)(m0 + 8) * DD + col) = make_float2(v2, v3);
            } else if (EPI == 0) {
                *(float2*)(Cp + (size_t)m0 * DD + col)       = make_float2(v0, v1);
                *(float2*)(Cp + (size_t)(m0 + 8) * DD + col) = make_float2(v2, v3);
            } else { // EPI == 2
                __half h0 = __float2half_rn(v0), h1 = __float2half_rn(v1);
                __half h2 = __float2half_rn(v2), h3 = __float2half_rn(v3);
                __half2 hv0(h0, h1), hv1(h2, h3);
                __half2 lv0(__float2half_rn(v0 - __half2float(h0)),
                            __float2half_rn(v1 - __half2float(h1)));
                __half2 lv1(__float2half_rn(v2 - __half2float(h2)),
                            __float2half_rn(v3 - __half2float(h3)));
                __half* r0 = xoutp + (size_t)m0 * KC + col;
                __half* r1 = xoutp + (size_t)(m0 + 8) * KC + col;
                *(__half2*)(r0)        = hv0;
                *(__half2*)(r0 + 512)  = lv0;
                *(__half2*)(r1)        = hv1;
                *(__half2*)(r1 + 512)  = lv1;
            }
        }
    }
}

// ---------------------------------------------------------------------------
// Fused scan phase (2 logical 128-thread units per 256-thread CTA).
// 512 logical units over 288 CTAs (576 halves; 512 active).
// ---------------------------------------------------------------------------
__device__ void scan_phase(const float* __restrict__ yin, const __half* __restrict__ yhalf,
                           const float* __restrict__ A, const float* __restrict__ Dskip, int bar0)
{
    extern __shared__ char smem[];
    int half = threadIdx.x >> 7;
    int ltid = threadIdx.x & 127;
    int u = blockIdx.x * 2 + half;
    bool act = (u < 512);
    float* sB = (float*)smem + half * 512;
    float* sC = (float*)smem + 1024 + half * 512;

    int xb = u & 3, c = (u >> 2) & 31, b = (u >> 7) & 3;
    int t0 = c * LCH;
    int d = xb * 128 + ltid;

    if (act) {
        const float4* srcB = (const float4*)(g_Bm + ((size_t)b * LL + t0) * NN);
        const float4* srcC = (const float4*)(g_Cm + ((size_t)b * LL + t0) * NN);
        ((float4*)sB)[ltid] = srcB[ltid];
        ((float4*)sC)[ltid] = srcC[ltid];
    }
    __syncthreads();

    float av[NN];
    const float* dtp = g_dt + ((size_t)b * LL + t0) * DD + d;
    const float*  ypf = yin   ? yin   + ((size_t)b * LL + t0) * DD + d : nullptr;
    const __half* yph = yhalf ? yhalf + ((size_t)b * LL + t0) * KC + d : nullptr;
    if (act) {
        #pragma unroll
        for (int q = 0; q < 4; q++)
            *(float4*)(av + q * 4) = *(const float4*)(A + (size_t)d * NN + q * 4);
    }

    // phase A
    if (act) {
        float h[NN], p[NN];
        #pragma unroll
        for (int n = 0; n < NN; n++) { h[n] = 0.f; p[n] = 1.f; }
        for (int t = 0; t < LCH; t++) {
            float dv = dtp[(size_t)t * DD];
            float yv = yph ? (__half2float(yph[(size_t)t * KC]) + __half2float(yph[(size_t)t * KC + 512]))
                           : ypf[(size_t)t * DD];
            float u2 = dv * yv;
            #pragma unroll
            for (int n = 0; n < NN; n++) {
                float e = __expf(dv * av[n]);
                p[n] *= e;
                h[n] = fmaf(e, h[n], u2 * sB[t * NN + n]);
            }
        }
        size_t o = (((size_t)b * NCH + c) * DD + d) * NN;
        #pragma unroll
        for (int q = 0; q < 4; q++) {
            *(float4*)(g_P  + o + q * 4) = *(float4*)(p + q * 4);
            *(float4*)(g_He + o + q * 4) = *(float4*)(h + q * 4);
        }
    }

    gbar(bar0);

    // phase B: 256 logical units of 128 threads
    if (u < 256) {
        int idx = u * 128 + ltid;
        int bb = idx >> 13;
        int dn = idx & 8191;
        size_t base = (size_t)bb * NCH * DD * NN + dn;
        float hc = 0.f;
        for (int g = 0; g < NCH; g += 8) {
            float p[8], he[8];
            #pragma unroll
            for (int j = 0; j < 8; j++) {
                p[j]  = g_P [base + (size_t)(g + j) * DD * NN];
                he[j] = g_He[base + (size_t)(g + j) * DD * NN];
            }
            #pragma unroll
            for (int j = 0; j < 8; j++) {
                g_carry[base + (size_t)(g + j) * DD * NN] = hc;
                hc = fmaf(p[j], hc, he[j]);
            }
        }
    }

    gbar(bar0 + 1);

    // phase C
    if (act) {
        float h[NN];
        size_t co = (((size_t)b * NCH + c) * DD + d) * NN;
        #pragma unroll
        for (int q = 0; q < 4; q++)
            *(float4*)(h + q * 4) = *(const float4*)(g_carry + co + q * 4);

        float ds = Dskip[d];
        __half* zb = g_Xcat1 + ((size_t)b * LL + t0) * KC + d;
        for (int t = 0; t < LCH; t++) {
            float dv = dtp[(size_t)t * DD];
            float yv = yph ? (__half2float(yph[(size_t)t * KC]) + __half2float(yph[(size_t)t * KC + 512]))
                           : ypf[(size_t)t * DD];
            float u2 = dv * yv;
            float acc = 0.f;
            #pragma unroll
            for (int n = 0; n < NN; n++) {
                float e = __expf(dv * av[n]);
                h[n] = fmaf(e, h[n], u2 * sB[t * NN + n]);
                acc = fmaf(h[n], sC[t * NN + n], acc);
            }
            float z = fmaxf(fmaf(ds, yv, acc), 0.f);
            __half hi = __float2half_rn(z);
            __half lo = __float2half_rn(z - __half2float(hi));
            __half* zr = zb + (size_t)t * KC;
            zr[0]   = hi;
            zr[512] = lo;
        }
    }
}

// ---------------------------------------------------------------------------
// Persistent mega kernel: 288 CTAs x 256 thr, 72KB smem, 2 CTA/SM (guaranteed).
// Phases separated by grid barriers (counters 0..8).
// ---------------------------------------------------------------------------
__global__ void __launch_bounds__(256, 2)
mega_k(const float* __restrict__ x, const float* __restrict__ A,
       const float* __restrict__ Dskip, const float* __restrict__ bB,
       const float* __restrict__ bC, const float* __restrict__ bdt,
       const float* __restrict__ blin, float* __restrict__ out)
{
    int p = blockIdx.x;
    const size_t WCSZ = (size_t)NW * KC;

    // P1: layer-0 dt GEMM (288 tiles) + F = Wlin2 @ Wdec (32 tiles on p<32)
    gemm_tile<1>((p % 9) * 64, (p / 9) * 128, g_Xcat0, g_Wcat,
                 bdt, bB, bC, nullptr, nullptr);
    if (p < 32)
        gemm_tile<3>((p & 7) * 64, (p >> 3) * 128, g_Xcat1, g_Wcat + 3 * WCSZ,
                     nullptr, nullptr, nullptr, nullptr, nullptr);
    gbar(0);

    // P2: layer-0 scan (bars 1,2)
    scan_phase(x, nullptr, A, Dskip, 1);
    gbar(3);

    // P3: layer-0 lin GEMM, fp16-split epilogue -> Xcat0 (256 tiles)
    if (p < 256)
        gemm_tile<2>((p & 7) * 64, (p >> 3) * 128, g_Xcat1, g_Wcat + 2 * WCSZ,
                     blin, nullptr, nullptr, nullptr, g_Xcat0);
    gbar(4);

    // P4: layer-1 dt GEMM (288 tiles)
    gemm_tile<1>((p % 9) * 64, (p / 9) * 128, g_Xcat0, g_Wcat + 1 * WCSZ,
                 bdt + DD, bB + NN, bC + NN, nullptr, nullptr);
    gbar(5);

    // P5: layer-1 scan (bars 6,7); y from Xcat0 halves
    scan_phase(nullptr, g_Xcat0, A + (size_t)DD * NN, Dskip + DD, 6);
    gbar(8);

    // P6: fused lin2+dec: out = z2 @ F + beff (256 tiles)
    if (p < 256)
        gemm_tile<0>((p & 7) * 64, (p >> 3) * 128, g_Xcat1, g_Wcat + 4 * WCSZ,
                     g_beff, nullptr, nullptr, out, nullptr);
}

// ---------------------------------------------------------------------------
// Merged prep kernel. grid (16, 16, 8), block 256.
// ---------------------------------------------------------------------------
__global__ void prep_k(const float* __restrict__ Wdt, const float* __restrict__ Wlin,
                       const float* __restrict__ Wdec, const float* __restrict__ WB,
                       const float* __restrict__ WC, const float* __restrict__ blin,
                       const float* __restrict__ bdec, const float4* __restrict__ x)
{
    __shared__ float t[32][33];
    __shared__ float part[32][8];
    int z = blockIdx.z;
    int bx = blockIdx.x, by = blockIdx.y;
    int tid = threadIdx.x;
    int tx = tid & 31, ty = tid >> 5;
    int bid = by * 16 + bx;

    if (z < 4) {
        const float* W = (z == 0) ? Wdt
                       : (z == 1) ? Wdt + (size_t)DD * DD
                       : (z == 2) ? Wlin
                                  : Wdec;
        __half* out = g_Wcat + (size_t)z * NW * KC;
        int bk = bx * 32, bn = by * 32;
        #pragma unroll
        for (int i = 0; i < 32; i += 8)
            t[ty + i][tx] = W[(size_t)(bk + ty + i) * DD + bn + tx];
        __syncthreads();
        #pragma unroll
        for (int i = 0; i < 32; i += 8) {
            float v = t[tx][ty + i];
            __half h = __float2half_rn(v);
            size_t o = (size_t)(bn + ty + i) * KC + bk + tx;
            out[o]       = h;
            out[o + 512] = h;
        }
    } else if (z == 4) {
        if (by >= 2) return;
        int l = by;
        int bk = bx * 32;
        __half* out = g_Wcat + (size_t)l * NW * KC + (size_t)512 * KC;
        for (int r = ty; r < 64; r += 8) {
            float v = 0.f;
            if (r < 16)      v = WB[(size_t)l * DD * NN + (size_t)(bk + tx) * NN + r];
            else if (r < 32) v = WC[(size_t)l * DD * NN + (size_t)(bk + tx) * NN + (r - 16)];
            __half h = __float2half_rn(v);
            size_t o = (size_t)r * KC + bk + tx;
            out[o]       = h;
            out[o + 512] = h;
        }
    } else if (z == 5) {
        const float4* in = (const float4*)(Wlin + (size_t)DD * DD);
        int i = bid * 256 + tid;
        int m = i >> 7;
        int k4 = (i & 127) << 2;
        float4 v = in[i];
        __half2 h0(__float2half_rn(v.x), __float2half_rn(v.y));
        __half2 h1(__float2half_rn(v.z), __float2half_rn(v.w));
        __half2 l0(__float2half_rn(v.x - __half2float(h0.x)),
                   __float2half_rn(v.y - __half2float(h0.y)));
        __half2 l1(__float2half_rn(v.z - __half2float(h1.x)),
                   __float2half_rn(v.w - __half2float(h1.y)));
        __half* row = g_Xcat1 + (size_t)m * KC;
        *(__half2*)(row + k4)       = h0;
        *(__half2*)(row + k4 + 2)   = h1;
        *(__half2*)(row + k4 + 512) = l0;
        *(__half2*)(row + k4 + 514) = l1;
    } else if (z == 6) {
        if (bid == 0 && tid < 12) g_barc[tid] = 0;
        if (bid >= 64) return;
        const float* blin2 = blin + DD;
        int og = tid & 7;
        int r  = tid >> 3;
        int o  = bid * 8 + og;
        float acc = 0.f;
        int d0 = r * 16;
        #pragma unroll
        for (int d = d0; d < d0 + 16; d++)
            acc = fmaf(blin2[d], Wdec[(size_t)d * DD + o], acc);
        part[r][og] = acc;
        __syncthreads();
        if (tid < 8) {
            float s = bdec[bid * 8 + tid];
            #pragma unroll
            for (int i = 0; i < 32; i++) s += part[i][tid];
            g_beff[bid * 8 + tid] = s;
        }
    } else {
        #pragma unroll
        for (int it = 0; it < 8; it++) {
            int i = (bid * 8 + it) * 256 + tid;
            int m = i >> 7;
            int k4 = (i & 127) << 2;
            float4 v = x[i];
            __half2 h0(__float2half_rn(v.x), __float2half_rn(v.y));
            __half2 h1(__float2half_rn(v.z), __float2half_rn(v.w));
            __half2 l0(__float2half_rn(v.x - __half2float(h0.x)),
                       __float2half_rn(v.y - __half2float(h0.y)));
            __half2 l1(__float2half_rn(v.z - __half2float(h1.x)),
                       __float2half_rn(v.w - __half2float(h1.y)));
            __half* row = g_Xcat0 + (size_t)m * KC;
            *(__half2*)(row + k4)       = h0;
            *(__half2*)(row + k4 + 2)   = h1;
            *(__half2*)(row + k4 + 512) = l0;
            *(__half2*)(row + k4 + 514) = l1;
        }
    }
}

// ---------------------------------------------------------------------------
// Host launcher (2 graph nodes)
// ---------------------------------------------------------------------------
extern "C" void kernel_launch(void* const* d_in, const int* in_sizes, int n_in,
                              void* d_out, int out_size)
{
    const float* x     = (const float*)d_in[0];
    const float* A     = (const float*)d_in[1];
    const float* Dskip = (const float*)d_in[2];
    const float* WB    = (const float*)d_in[3];
    const float* bB    = (const float*)d_in[4];
    const float* WC    = (const float*)d_in[5];
    const float* bC    = (const float*)d_in[6];
    const float* Wdt   = (const float*)d_in[7];
    const float* bdt   = (const float*)d_in[8];
    const float* Wlin  = (const float*)d_in[9];
    const float* blin  = (const float*)d_in[10];
    const float* Wdec  = (const float*)d_in[11];
    const float* bdec  = (const float*)d_in[12];
    float* out = (float*)d_out;

    cudaFuncSetAttribute(mega_k, cudaFuncAttributeMaxDynamicSharedMemorySize, TC_SMEM);

    // 1) prep: weight splits, x split, beff, barrier reset
    prep_k<<<dim3(16, 16, 8), 256>>>(Wdt, Wlin, Wdec, WB, WC, blin, bdec, (const float4*)x);

    // 2) persistent fused pipeline
    mega_k<<<NBAR, 256, TC_SMEM>>>(x, A, Dskip, bB, bC, bdt, blin, out);
}